// round 14
// baseline (speedup 1.0000x reference)
#include <cuda_runtime.h>
#include <cuda_fp16.h>
#include <math.h>
#include <stdint.h>

// ---------------- problem constants ----------------
#define TLEN 1024
#define DIMP 1024
#define DIN  2048
#define NSTATE 16
#define TSUM (1024+512+256)
#define TB 8                 // t-rows per ssm_front block

// ---------------- fp32 scratch ----------------
__device__ __align__(128) float g_xz   [TLEN*4096];
__device__ __align__(128) float g_x1   [512*DIN];
__device__ __align__(128) float g_x2   [256*DIN];
__device__ __align__(128) float g_xc   [TSUM*DIN];
__device__ __align__(128) float g_proj [TSUM*32];
__device__ __align__(128) float g_dt   [TSUM*DIN];
__device__ __align__(128) float g_y    [TSUM*DIN];
__device__ __align__(128) float g_fused[TLEN*DIN];
__device__ __align__(128) float g_yres [TLEN*DIMP];

// ---------------- fp16 operand scratch ----------------
__device__ __align__(128) __half g_xh  [TLEN*DIMP];
__device__ __align__(128) __half g_ctxh[TLEN*DIN];
__device__ __align__(128) __half g_g1h [TLEN*DIMP];
__device__ __align__(128) __half g_preh[TLEN*DIN];
__device__ __align__(128) __half g_w0h [4096*DIMP];
__device__ __align__(128) __half g_w1h [DIMP*DIN];
__device__ __align__(128) __half g_w2h [DIN*DIMP];
__device__ __align__(128) __half g_w3h [DIMP*DIN];

// ---------------- helpers ----------------
__device__ __forceinline__ float sigmoidf_(float x) { return 1.0f / (1.0f + expf(-x)); }
__device__ __forceinline__ float siluf_(float x)    { return x / (1.0f + expf(-x)); }
__device__ __forceinline__ float softplusf_(float x) {
    return fmaxf(x, 0.0f) + log1pf(expf(-fabsf(x)));
}
__device__ __forceinline__ uint32_t smem_u32(const void* p) {
    uint32_t a;
    asm("{ .reg .u64 t; cvta.to.shared.u64 t, %1; cvt.u32.u64 %0, t; }" : "=r"(a) : "l"(p));
    return a;
}
__device__ __forceinline__ void cp16(uint32_t dst, const void* src) {
    asm volatile("cp.async.cg.shared.global [%0], [%1], 16;" :: "r"(dst), "l"(src));
}

// ---------------- merged fp32 -> fp16 conversion (MLP=4) ----------------
#define CVT_U0 65536
#define CVT_U1 262144
#define CVT_U2 131072
#define CVT_U3 131072
#define CVT_U4 131072
#define CVT_UNITS (CVT_U0+CVT_U1+CVT_U2+CVT_U3+CVT_U4)

__global__ __launch_bounds__(256)
void cvt_all_kernel(const float* __restrict__ s0, __half* __restrict__ d0,
                    const float* __restrict__ s1, __half* __restrict__ d1,
                    const float* __restrict__ s2, __half* __restrict__ d2,
                    const float* __restrict__ s3, __half* __restrict__ d3,
                    const float* __restrict__ s4, __half* __restrict__ d4)
{
    int u = blockIdx.x * 256 + threadIdx.x;
    const float4* s; uint2* d; int off;
    if (u < CVT_U0)                          { s = (const float4*)s0; d = (uint2*)d0; off = u; }
    else if (u < CVT_U0+CVT_U1)              { s = (const float4*)s1; d = (uint2*)d1; off = u - CVT_U0; }
    else if (u < CVT_U0+CVT_U1+CVT_U2)       { s = (const float4*)s2; d = (uint2*)d2; off = u - (CVT_U0+CVT_U1); }
    else if (u < CVT_U0+CVT_U1+CVT_U2+CVT_U3){ s = (const float4*)s3; d = (uint2*)d3; off = u - (CVT_U0+CVT_U1+CVT_U2); }
    else                                     { s = (const float4*)s4; d = (uint2*)d4; off = u - (CVT_U0+CVT_U1+CVT_U2+CVT_U3); }
    float4 v[4];
#pragma unroll
    for (int j = 0; j < 4; j++) v[j] = s[(size_t)off * 4 + j];
#pragma unroll
    for (int j = 0; j < 4; j++) {
        __half2 h01 = __floats2half2_rn(v[j].x, v[j].y);
        __half2 h23 = __floats2half2_rn(v[j].z, v[j].w);
        uint2 hv; hv.x = *(uint32_t*)&h01; hv.y = *(uint32_t*)&h23;
        d[(size_t)off * 4 + j] = hv;
    }
}

// ============ tensor-core GEMM: C = A(fp16) @ B(fp16)^T, fp32 accum ==========
#define MMA_F16(c, a, b) \
  asm volatile("mma.sync.aligned.m16n8k16.row.col.f32.f16.f16.f32 " \
      "{%0,%1,%2,%3}, {%4,%5,%6,%7}, {%8,%9}, {%0,%1,%2,%3};" \
      : "+f"((c)[0]), "+f"((c)[1]), "+f"((c)[2]), "+f"((c)[3]) \
      : "r"((a)[0]), "r"((a)[1]), "r"((a)[2]), "r"((a)[3]), \
        "r"((b)[0]), "r"((b)[1]))

#define LDSM_X4(r, addr) \
  asm volatile("ldmatrix.sync.aligned.m8n8.x4.shared.b16 {%0,%1,%2,%3}, [%4];" \
      : "=r"((r)[0]), "=r"((r)[1]), "=r"((r)[2]), "=r"((r)[3]) : "r"(addr))

#define GPAD 72

template<int EPI, int BM_T, int NS>
__global__ __launch_bounds__(256, 2)
void gemm_mma(const __half* __restrict__ A, const __half* __restrict__ B,
              float* __restrict__ C, __half* __restrict__ Ch,
              const float* __restrict__ Res, const float* __restrict__ Gate,
              int M, int N, int K)
{
    constexpr int A_EL  = BM_T * GPAD;
    constexpr int B_EL  = 128 * GPAD;
    constexpr int STAGE = A_EL + B_EL;
    constexpr int MI    = BM_T / 32;

    extern __shared__ __half dyn[];
    const uint32_t dynb = smem_u32(dyn);

    const int tid  = threadIdx.x;
    const int warp = tid >> 5;
    const int lane = tid & 31;
    const int g    = lane >> 2;
    const int tig  = lane & 3;
    const int wm   = (warp >> 2) * (BM_T / 2);
    const int wn   = (warp & 3) * 32;
    const int bm   = blockIdx.y * BM_T;
    const int bn   = blockIdx.x * 128;

    const int lh = lane & 15;
    const int kh = (lane >> 4) << 3;
    const uint32_t aoff = (uint32_t)((wm + lh) * GPAD + kh) * 2;
    const uint32_t boff = (uint32_t)((wn + lh) * GPAD + kh) * 2;

    float acc[MI][4][4];
#pragma unroll
    for (int mi = 0; mi < MI; mi++)
#pragma unroll
        for (int ni = 0; ni < 4; ni++)
#pragma unroll
            for (int q = 0; q < 4; q++) acc[mi][ni][q] = 0.0f;

    const int NC = K >> 6;

    auto issue = [&](int stg, int k0) {
        const uint32_t sb = dynb + stg * STAGE * 2;
#pragma unroll
        for (int i = 0; i < BM_T / 32; i++) {
            int c = tid + i * 256;
            int row = c >> 3, cc = (c & 7) << 3;
            cp16(sb + (uint32_t)(row * GPAD + cc) * 2,
                 A + (size_t)(bm + row) * K + k0 + cc);
        }
#pragma unroll
        for (int i = 0; i < 4; i++) {
            int c = tid + i * 256;
            int row = c >> 3, cc = (c & 7) << 3;
            cp16(sb + (uint32_t)(A_EL + row * GPAD + cc) * 2,
                 B + (size_t)(bn + row) * K + k0 + cc);
        }
        asm volatile("cp.async.commit_group;" ::: "memory");
    };

#pragma unroll
    for (int p = 0; p < NS - 1; p++) issue(p, p << 6);

    for (int c = 0; c < NC; c++) {
        asm volatile("cp.async.wait_group %0;" :: "n"(NS - 2) : "memory");
        __syncthreads();
        {
            int nk = c + NS - 1;
            issue(nk % NS, (nk < NC ? nk : NC - 1) << 6);
        }

        const uint32_t sb = dynb + (c % NS) * STAGE * 2;
        const uint32_t aS = sb;
        const uint32_t bS = sb + A_EL * 2;

#pragma unroll
        for (int ks = 0; ks < 64; ks += 16) {
            const uint32_t ko = (uint32_t)ks * 2;
            uint32_t afr[MI][4], bh[4][2];
#pragma unroll
            for (int mi = 0; mi < MI; mi++)
                LDSM_X4(afr[mi], aS + aoff + (uint32_t)(mi * 16 * GPAD) * 2 + ko);
#pragma unroll
            for (int p = 0; p < 2; p++) {
                uint32_t r[4];
                LDSM_X4(r, bS + boff + (uint32_t)(p * 16 * GPAD) * 2 + ko);
                bh[2 * p][0] = r[0]; bh[2 * p][1] = r[2];
                bh[2 * p + 1][0] = r[1]; bh[2 * p + 1][1] = r[3];
            }
#pragma unroll
            for (int mi = 0; mi < MI; mi++)
#pragma unroll
                for (int ni = 0; ni < 4; ni++)
                    MMA_F16(acc[mi][ni], afr[mi], bh[ni]);
        }
    }
    asm volatile("cp.async.wait_group 0;" ::: "memory");

    // ---- epilogue ----
#pragma unroll
    for (int mi = 0; mi < MI; mi++) {
        int row = bm + wm + mi * 16 + g;
#pragma unroll
        for (int ni = 0; ni < 4; ni++) {
            int col = bn + wn + ni * 8 + tig * 2;
            float v0 = acc[mi][ni][0], v1 = acc[mi][ni][1];
            float v2 = acc[mi][ni][2], v3 = acc[mi][ni][3];
            if (EPI == 1) {
                v0 = siluf_(v0); v1 = siluf_(v1); v2 = siluf_(v2); v3 = siluf_(v3);
                *(__half2*)(Ch + (size_t)row * N + col)       = __floats2half2_rn(v0, v1);
                *(__half2*)(Ch + (size_t)(row + 8) * N + col) = __floats2half2_rn(v2, v3);
            } else if (EPI == 4) {
                float2 f0 = *(const float2*)(Res + (size_t)row * N + col);
                float2 f1 = *(const float2*)(Res + (size_t)(row + 8) * N + col);
                float2 gv0 = *(const float2*)(Gate + (size_t)row * 4096 + 2048 + col);
                float2 gv1 = *(const float2*)(Gate + (size_t)(row + 8) * 4096 + 2048 + col);
                float p0 = f0.x * sigmoidf_(v0) * siluf_(gv0.x);
                float p1 = f0.y * sigmoidf_(v1) * siluf_(gv0.y);
                float p2 = f1.x * sigmoidf_(v2) * siluf_(gv1.x);
                float p3 = f1.y * sigmoidf_(v3) * siluf_(gv1.y);
                *(__half2*)(Ch + (size_t)row * N + col)       = __floats2half2_rn(p0, p1);
                *(__half2*)(Ch + (size_t)(row + 8) * N + col) = __floats2half2_rn(p2, p3);
            } else {
                if (EPI == 3) {
                    const float2 r0v = *(const float2*)(Res + (size_t)row * N + col);
                    const float2 r1v = *(const float2*)(Res + (size_t)(row + 8) * N + col);
                    v0 += r0v.x; v1 += r0v.y; v2 += r1v.x; v3 += r1v.y;
                }
                float2 o0; o0.x = v0; o0.y = v1;
                float2 o1; o1.x = v2; o1.y = v3;
                *(float2*)(C + (size_t)row * N + col)       = o0;
                *(float2*)(C + (size_t)(row + 8) * N + col) = o1;
            }
        }
    }
}

// ---------------- merged downsample ----------------
__global__ void down_all(const float* __restrict__ xz, float* __restrict__ o1,
                         float* __restrict__ o2)
{
    int idx = blockIdx.x * blockDim.x + threadIdx.x;
    if (idx < 512 * DIN) {
        int t = idx >> 11, d = idx & 2047;
        o1[idx] = 0.5f * (xz[(size_t)(2 * t) * 4096 + d] + xz[(size_t)(2 * t + 1) * 4096 + d]);
    } else {
        int r = idx - 512 * DIN;
        int t = r >> 11, d = r & 2047;
        float s = xz[(size_t)(4 * t) * 4096 + d] + xz[(size_t)(4 * t + 1) * 4096 + d]
                + xz[(size_t)(4 * t + 2) * 4096 + d] + xz[(size_t)(4 * t + 3) * 4096 + d];
        o2[r] = 0.25f * s;
    }
}

// ---------------- fused SSM front, TB=8 t-rows per block ----------------------
// grid: 128 (scale0) + 64 (scale1) + 32 (scale2) = 224 blocks of 256 threads.
// smem: sxc[TB][DIN] fp32 (64KB) + sB[TB][16].
__global__ __launch_bounds__(256)
void ssm_front_tb(const float* __restrict__ xz, const float* __restrict__ x1,
                  const float* __restrict__ x2,
                  const float* __restrict__ cw, const float* __restrict__ cb,
                  const float* __restrict__ xw,
                  const float* __restrict__ dtw, const float* __restrict__ dtb,
                  float* __restrict__ xc, float* __restrict__ proj,
                  float* __restrict__ dt)
{
    extern __shared__ float sm[];
    float* sxc = sm;                 // TB*DIN
    float* sB  = sm + TB * DIN;      // TB*16

    const int blk = blockIdx.x;
    int sc, t0, xs; const float* src;
    if (blk < 128)      { sc = 0; t0 = blk * TB;         src = xz; xs = 4096; }
    else if (blk < 192) { sc = 1; t0 = (blk - 128) * TB; src = x1; xs = 2048; }
    else                { sc = 2; t0 = (blk - 192) * TB; src = x2; xs = 2048; }
    const int tg0 = (sc == 0 ? 0 : (sc == 1 ? 1024 : 1536)) + t0;

    // ---- stage 1: depthwise conv + silu for TB rows ----
#pragma unroll
    for (int i = 0; i < 8; i++) {
        int d = threadIdx.x + i * 256;
        float4 wv = *(const float4*)(cw + (size_t)sc * DIN * 4 + d * 4);
        float bb  = cb[sc * DIN + d];
#pragma unroll
        for (int r = 0; r < TB; r++) {
            int trow = t0 + r;
            float acc = bb;
            if (trow >= 3) acc = fmaf(src[(size_t)(trow - 3) * xs + d], wv.x, acc);
            if (trow >= 2) acc = fmaf(src[(size_t)(trow - 2) * xs + d], wv.y, acc);
            if (trow >= 1) acc = fmaf(src[(size_t)(trow - 1) * xs + d], wv.z, acc);
            acc = fmaf(src[(size_t)trow * xs + d], wv.w, acc);
            float v = acc * sigmoidf_(acc);
            sxc[r * DIN + d] = v;
            xc[(size_t)(tg0 + r) * DIN + d] = v;
        }
    }
    __syncthreads();

    // ---- stage 2: xproj — warp computes 4 outputs x TB rows, weights once ----
    {
        int warp = threadIdx.x >> 5, lane = threadIdx.x & 31;
        const float* wbase = xw + (size_t)sc * 32 * DIN;
        const float* w0 = wbase + (size_t)(warp * 4 + 0) * DIN;
        const float* w1 = wbase + (size_t)(warp * 4 + 1) * DIN;
        const float* w2 = wbase + (size_t)(warp * 4 + 2) * DIN;
        const float* w3 = wbase + (size_t)(warp * 4 + 3) * DIN;
        float a[4][TB];
#pragma unroll
        for (int j = 0; j < 4; j++)
#pragma unroll
            for (int r = 0; r < TB; r++) a[j][r] = 0.0f;
        for (int k = lane; k < DIN; k += 32) {
            float wv0 = w0[k], wv1 = w1[k], wv2 = w2[k], wv3 = w3[k];
#pragma unroll
            for (int r = 0; r < TB; r++) {
                float xv = sxc[r * DIN + k];
                a[0][r] = fmaf(xv, wv0, a[0][r]);
                a[1][r] = fmaf(xv, wv1, a[1][r]);
                a[2][r] = fmaf(xv, wv2, a[2][r]);
                a[3][r] = fmaf(xv, wv3, a[3][r]);
            }
        }
#pragma unroll
        for (int o = 16; o > 0; o >>= 1)
#pragma unroll
            for (int j = 0; j < 4; j++)
#pragma unroll
                for (int r = 0; r < TB; r++)
                    a[j][r] += __shfl_xor_sync(0xffffffffu, a[j][r], o);
        if (lane == 0) {
            int o0 = warp * 4;
#pragma unroll
            for (int r = 0; r < TB; r++) {
#pragma unroll
                for (int j = 0; j < 4; j++)
                    proj[(tg0 + r) * 32 + o0 + j] = a[j][r];
                if (o0 < 16) {
#pragma unroll
                    for (int j = 0; j < 4; j++) sB[r * 16 + o0 + j] = a[j][r];
                }
            }
        }
    }
    __syncthreads();

    // ---- stage 3: dt — dtw loads hoisted out of the row loop ----
#pragma unroll
    for (int i = 0; i < 8; i++) {
        int d = threadIdx.x + i * 256;
        const float4* wp = (const float4*)(dtw + (size_t)sc * DIN * 16 + (size_t)d * 16);
        float4 w0 = wp[0], w1 = wp[1], w2 = wp[2], w3 = wp[3];
        float bb = dtb[sc * DIN + d];
#pragma unroll
        for (int r = 0; r < TB; r++) {
            const float* B = sB + r * 16;
            float acc = bb;
            acc = fmaf(B[0],  w0.x, acc); acc = fmaf(B[1],  w0.y, acc);
            acc = fmaf(B[2],  w0.z, acc); acc = fmaf(B[3],  w0.w, acc);
            acc = fmaf(B[4],  w1.x, acc); acc = fmaf(B[5],  w1.y, acc);
            acc = fmaf(B[6],  w1.z, acc); acc = fmaf(B[7],  w1.w, acc);
            acc = fmaf(B[8],  w2.x, acc); acc = fmaf(B[9],  w2.y, acc);
            acc = fmaf(B[10], w2.z, acc); acc = fmaf(B[11], w2.w, acc);
            acc = fmaf(B[12], w3.x, acc); acc = fmaf(B[13], w3.y, acc);
            acc = fmaf(B[14], w3.z, acc); acc = fmaf(B[15], w3.w, acc);
            dt[(size_t)(tg0 + r) * DIN + d] = softplusf_(softplusf_(acc));
        }
    }
}

// ---------------- merged selective scan (all scales, 4-t batched) -------------
__global__ __launch_bounds__(256)
void scan_all(const float* __restrict__ dt, const float* __restrict__ xc,
              const float* __restrict__ proj, const float* __restrict__ Dp,
              float* __restrict__ y)
{
    int gid = blockIdx.x * blockDim.x + threadIdx.x;
    int sc  = gid >> 15;
    int r   = gid & 32767;
    int d = r >> 4;
    int s = r & 15;
    const int T    = (sc == 0) ? 1024 : (sc == 1 ? 512 : 256);
    const int toff = (sc == 0) ? 0 : (sc == 1 ? 1024 : 1536);
    const float* dts = dt   + (size_t)toff * DIN;
    const float* xcs = xc   + (size_t)toff * DIN;
    const float* prs = proj + (size_t)toff * 32;
    float*       ys  = y    + (size_t)toff * DIN;
    const float A = -(float)(s + 1);
    const float Dd = Dp[sc * DIN + d];
    float h = 0.0f;
    for (int t0 = 0; t0 < T; t0 += 4) {
        float v[4], xcv[4], dtv[4], Bv[4], Cv[4];
#pragma unroll
        for (int j = 0; j < 4; j++) {
            int t = t0 + j;
            dtv[j] = dts[(size_t)t * DIN + d];
            xcv[j] = xcs[(size_t)t * DIN + d];
            Bv[j]  = prs[t * 32 + s];
            Cv[j]  = prs[t * 32 + 16 + s];
        }
#pragma unroll
        for (int j = 0; j < 4; j++) {
            float da  = fmaxf(expf(dtv[j] * A), 1e-38f);
            float dbx = fmaxf(dtv[j] * Bv[j] * xcv[j], 1e-38f);
            h = fmaf(da, h, dbx);
            v[j] = Cv[j] * h;
        }
#pragma unroll
        for (int o = 8; o > 0; o >>= 1) {
            v[0] += __shfl_xor_sync(0xffffffffu, v[0], o, 16);
            v[1] += __shfl_xor_sync(0xffffffffu, v[1], o, 16);
            v[2] += __shfl_xor_sync(0xffffffffu, v[2], o, 16);
            v[3] += __shfl_xor_sync(0xffffffffu, v[3], o, 16);
        }
        if (s == 0) {
#pragma unroll
            for (int j = 0; j < 4; j++)
                ys[(size_t)(t0 + j) * DIN + d] = v[j] + Dd * xcv[j];
        }
    }
}

// ---------------- fuse ----------------
__global__ void fuse_kernel(const float* __restrict__ y0, const float* __restrict__ y1,
                            const float* __restrict__ y2, const float* __restrict__ sw,
                            float* __restrict__ fused, __half* __restrict__ ctxh)
{
    int idx = blockIdx.x * blockDim.x + threadIdx.x;
    int t = idx >> 11, d = idx & 2047;

    float o0 = y0[idx];

    float p1 = fminf(fmaxf(0.5f * (float)t - 0.25f, 0.0f), 511.0f);
    int lo1 = (int)floorf(p1);
    int hi1 = min(lo1 + 1, 511);
    float w1 = p1 - (float)lo1;
    float o1 = y1[(size_t)lo1 * DIN + d] * (1.0f - w1) + y1[(size_t)hi1 * DIN + d] * w1;

    float p2 = fminf(fmaxf(0.25f * (float)t - 0.375f, 0.0f), 255.0f);
    int lo2 = (int)floorf(p2);
    int hi2 = min(lo2 + 1, 255);
    float w2 = p2 - (float)lo2;
    float o2 = y2[(size_t)lo2 * DIN + d] * (1.0f - w2) + y2[(size_t)hi2 * DIN + d] * w2;

    float s0 = sw[0], s1 = sw[1], s2 = sw[2];
    float m = fmaxf(s0, fmaxf(s1, s2));
    float e0 = expf(s0 - m), e1 = expf(s1 - m), e2 = expf(s2 - m);
    float inv = 1.0f / (e0 + e1 + e2);

    fused[idx] = e0 * inv * o0 + e1 * inv * o1 + e2 * inv * o2;
    ctxh[idx]  = __float2half_rn((o0 + o1 + o2) * (1.0f / 3.0f));
}

// ---------------- layernorm ----------------
__global__ __launch_bounds__(256)
void ln_kernel(const float* __restrict__ y, const float* __restrict__ g,
               const float* __restrict__ b, float* __restrict__ out)
{
    int t = blockIdx.x;
    const float* yr = y + (size_t)t * DIMP;
    float vals[4];
    float s = 0.0f, s2 = 0.0f;
#pragma unroll
    for (int i = 0; i < 4; i++) {
        float v = yr[threadIdx.x + i * 256];
        vals[i] = v; s += v; s2 += v * v;
    }
#pragma unroll
    for (int o = 16; o > 0; o >>= 1) {
        s  += __shfl_xor_sync(0xffffffffu, s, o);
        s2 += __shfl_xor_sync(0xffffffffu, s2, o);
    }
    __shared__ float rs[8], rs2[8];
    int warp = threadIdx.x >> 5, lane = threadIdx.x & 31;
    if (lane == 0) { rs[warp] = s; rs2[warp] = s2; }
    __syncthreads();
    if (threadIdx.x == 0) {
        float S = 0, S2 = 0;
#pragma unroll
        for (int i = 0; i < 8; i++) { S += rs[i]; S2 += rs2[i]; }
        rs[0] = S; rs2[0] = S2;
    }
    __syncthreads();
    float mu  = rs[0] * (1.0f / 1024.0f);
    float var = rs2[0] * (1.0f / 1024.0f) - mu * mu;
    float rstd = rsqrtf(var + 1e-5f);
#pragma unroll
    for (int i = 0; i < 4; i++) {
        int j = threadIdx.x + i * 256;
        out[(size_t)t * DIMP + j] = (vals[i] - mu) * rstd * g[j] + b[j];
    }
}

// ---------------- launch ------------------------------------------------------
extern "C" void kernel_launch(void* const* d_in, const int* in_sizes, int n_in,
                              void* d_out, int out_size)
{
    const float* x          = (const float*)d_in[0];
    const float* in_proj_w  = (const float*)d_in[1];
    const float* conv_w     = (const float*)d_in[2];
    const float* conv_b     = (const float*)d_in[3];
    const float* xproj_w    = (const float*)d_in[4];
    const float* dtproj_w   = (const float*)d_in[5];
    const float* dtproj_b   = (const float*)d_in[6];
    const float* D_param    = (const float*)d_in[7];
    const float* scale_w    = (const float*)d_in[8];
    const float* gate_w1    = (const float*)d_in[9];
    const float* gate_w2    = (const float*)d_in[10];
    const float* out_proj_w = (const float*)d_in[11];
    const float* ln_g       = (const float*)d_in[12];
    const float* ln_b       = (const float*)d_in[13];
    float* out = (float*)d_out;

    float *xz, *x1, *x2, *xc, *proj, *dt, *yb, *fused, *yres;
    cudaGetSymbolAddress((void**)&xz,   g_xz);
    cudaGetSymbolAddress((void**)&x1,   g_x1);
    cudaGetSymbolAddress((void**)&x2,   g_x2);
    cudaGetSymbolAddress((void**)&xc,   g_xc);
    cudaGetSymbolAddress((void**)&proj, g_proj);
    cudaGetSymbolAddress((void**)&dt,   g_dt);
    cudaGetSymbolAddress((void**)&yb,   g_y);
    cudaGetSymbolAddress((void**)&fused,g_fused);
    cudaGetSymbolAddress((void**)&yres, g_yres);

    __half *xh,*ctxh,*g1h,*preh,*w0h,*w1h,*w2h,*w3h;
    cudaGetSymbolAddress((void**)&xh,  g_xh);
    cudaGetSymbolAddress((void**)&ctxh,g_ctxh);
    cudaGetSymbolAddress((void**)&g1h, g_g1h);
    cudaGetSymbolAddress((void**)&preh,g_preh);
    cudaGetSymbolAddress((void**)&w0h, g_w0h);
    cudaGetSymbolAddress((void**)&w1h, g_w1h);
    cudaGetSymbolAddress((void**)&w2h, g_w2h);
    cudaGetSymbolAddress((void**)&w3h, g_w3h);

    constexpr int SM128 = (128 * GPAD + 128 * GPAD) * 2 * 3;  // 110592 B
    constexpr int SM64  = (64  * GPAD + 128 * GPAD) * 2 * 4;  // 110592 B
    constexpr int SMFRONT = (TB * DIN + TB * 16) * 4;         // 66048 B
    cudaFuncSetAttribute(gemm_mma<0,128,3>, cudaFuncAttributeMaxDynamicSharedMemorySize, SM128);
    cudaFuncSetAttribute(gemm_mma<1,64,4>,  cudaFuncAttributeMaxDynamicSharedMemorySize, SM64);
    cudaFuncSetAttribute(gemm_mma<4,64,4>,  cudaFuncAttributeMaxDynamicSharedMemorySize, SM64);
    cudaFuncSetAttribute(gemm_mma<3,64,4>,  cudaFuncAttributeMaxDynamicSharedMemorySize, SM64);
    cudaFuncSetAttribute(ssm_front_tb,      cudaFuncAttributeMaxDynamicSharedMemorySize, SMFRONT);

    // 0) preconvert all fp16 operands in one launch
    cvt_all_kernel<<<CVT_UNITS / 256, 256>>>(x, xh, in_proj_w, w0h, gate_w1, w1h,
                                             gate_w2, w2h, out_proj_w, w3h);

    // 1) xz = x @ in_proj_w^T
    gemm_mma<0,128,3><<<dim3(32, 8), 256, SM128>>>(xh, w0h, xz, nullptr, nullptr, nullptr,
                                                   1024, 4096, 1024);

    // 2) downsample (merged)
    down_all<<<(512 * DIN + 256 * DIN) / 256, 256>>>(xz, x1, x2);

    // 3) SSM front fused (TB=8 rows/block), then scan
    ssm_front_tb<<<224, 256, SMFRONT>>>(xz, x1, x2, conv_w, conv_b, xproj_w,
                                        dtproj_w, dtproj_b, xc, proj, dt);
    scan_all<<<(3 * DIN * NSTATE) / 256, 256>>>(dt, xc, proj, D_param, yb);

    // 4) fuse
    fuse_kernel<<<(TLEN * DIN) / 256, 256>>>(yb, yb + (size_t)1024 * DIN, yb + (size_t)1536 * DIN,
                                             scale_w, fused, ctxh);

    // 5) gating (pre fused into gemm2 epilogue)
    gemm_mma<1,64,4><<<dim3(8, 16), 256, SM64>>>(ctxh, w1h, nullptr, g1h, nullptr, nullptr,
                                                 1024, 1024, 2048);
    gemm_mma<4,64,4><<<dim3(16, 16), 256, SM64>>>(g1h, w2h, nullptr, preh, fused, xz,
                                                  1024, 2048, 1024);

    // 6) out_proj + residual
    gemm_mma<3,64,4><<<dim3(8, 16), 256, SM64>>>(preh, w3h, yres, nullptr, x, nullptr,
                                                 1024, 1024, 2048);

    // 7) layernorm
    ln_kernel<<<1024, 256>>>(yres, ln_g, ln_b, out);
}

// round 16
// speedup vs baseline: 1.1405x; 1.1405x over previous
#include <cuda_runtime.h>
#include <cuda_fp16.h>
#include <math.h>
#include <stdint.h>

// ---------------- problem constants ----------------
#define TLEN 1024
#define DIMP 1024
#define DIN  2048
#define NSTATE 16
#define TSUM (1024+512+256)
#define TB 4                 // t-rows per ssm_front block (TB=8 -> 228 regs, failed)

// ---------------- fp32 scratch ----------------
__device__ __align__(128) float g_xz   [TLEN*4096];
__device__ __align__(128) float g_x1   [512*DIN];
__device__ __align__(128) float g_x2   [256*DIN];
__device__ __align__(128) float g_xc   [TSUM*DIN];
__device__ __align__(128) float g_proj [TSUM*32];
__device__ __align__(128) float g_dt   [TSUM*DIN];
__device__ __align__(128) float g_y    [TSUM*DIN];
__device__ __align__(128) float g_fused[TLEN*DIN];
__device__ __align__(128) float g_yres [TLEN*DIMP];

// ---------------- fp16 operand scratch ----------------
__device__ __align__(128) __half g_xh  [TLEN*DIMP];
__device__ __align__(128) __half g_ctxh[TLEN*DIN];
__device__ __align__(128) __half g_g1h [TLEN*DIMP];
__device__ __align__(128) __half g_preh[TLEN*DIN];
__device__ __align__(128) __half g_w0h [4096*DIMP];
__device__ __align__(128) __half g_w1h [DIMP*DIN];
__device__ __align__(128) __half g_w2h [DIN*DIMP];
__device__ __align__(128) __half g_w3h [DIMP*DIN];

// ---------------- helpers ----------------
__device__ __forceinline__ float sigmoidf_(float x) { return 1.0f / (1.0f + expf(-x)); }
__device__ __forceinline__ float siluf_(float x)    { return x / (1.0f + expf(-x)); }
__device__ __forceinline__ float softplusf_(float x) {
    return fmaxf(x, 0.0f) + log1pf(expf(-fabsf(x)));
}
__device__ __forceinline__ uint32_t smem_u32(const void* p) {
    uint32_t a;
    asm("{ .reg .u64 t; cvta.to.shared.u64 t, %1; cvt.u32.u64 %0, t; }" : "=r"(a) : "l"(p));
    return a;
}
__device__ __forceinline__ void cp16(uint32_t dst, const void* src) {
    asm volatile("cp.async.cg.shared.global [%0], [%1], 16;" :: "r"(dst), "l"(src));
}

// ---------------- merged fp32 -> fp16 conversion (MLP=4) ----------------
#define CVT_U0 65536
#define CVT_U1 262144
#define CVT_U2 131072
#define CVT_U3 131072
#define CVT_U4 131072
#define CVT_UNITS (CVT_U0+CVT_U1+CVT_U2+CVT_U3+CVT_U4)

__global__ __launch_bounds__(256)
void cvt_all_kernel(const float* __restrict__ s0, __half* __restrict__ d0,
                    const float* __restrict__ s1, __half* __restrict__ d1,
                    const float* __restrict__ s2, __half* __restrict__ d2,
                    const float* __restrict__ s3, __half* __restrict__ d3,
                    const float* __restrict__ s4, __half* __restrict__ d4)
{
    int u = blockIdx.x * 256 + threadIdx.x;
    const float4* s; uint2* d; int off;
    if (u < CVT_U0)                          { s = (const float4*)s0; d = (uint2*)d0; off = u; }
    else if (u < CVT_U0+CVT_U1)              { s = (const float4*)s1; d = (uint2*)d1; off = u - CVT_U0; }
    else if (u < CVT_U0+CVT_U1+CVT_U2)       { s = (const float4*)s2; d = (uint2*)d2; off = u - (CVT_U0+CVT_U1); }
    else if (u < CVT_U0+CVT_U1+CVT_U2+CVT_U3){ s = (const float4*)s3; d = (uint2*)d3; off = u - (CVT_U0+CVT_U1+CVT_U2); }
    else                                     { s = (const float4*)s4; d = (uint2*)d4; off = u - (CVT_U0+CVT_U1+CVT_U2+CVT_U3); }
    float4 v[4];
#pragma unroll
    for (int j = 0; j < 4; j++) v[j] = s[(size_t)off * 4 + j];
#pragma unroll
    for (int j = 0; j < 4; j++) {
        __half2 h01 = __floats2half2_rn(v[j].x, v[j].y);
        __half2 h23 = __floats2half2_rn(v[j].z, v[j].w);
        uint2 hv; hv.x = *(uint32_t*)&h01; hv.y = *(uint32_t*)&h23;
        d[(size_t)off * 4 + j] = hv;
    }
}

// ============ tensor-core GEMM: C = A(fp16) @ B(fp16)^T, fp32 accum ==========
#define MMA_F16(c, a, b) \
  asm volatile("mma.sync.aligned.m16n8k16.row.col.f32.f16.f16.f32 " \
      "{%0,%1,%2,%3}, {%4,%5,%6,%7}, {%8,%9}, {%0,%1,%2,%3};" \
      : "+f"((c)[0]), "+f"((c)[1]), "+f"((c)[2]), "+f"((c)[3]) \
      : "r"((a)[0]), "r"((a)[1]), "r"((a)[2]), "r"((a)[3]), \
        "r"((b)[0]), "r"((b)[1]))

#define LDSM_X4(r, addr) \
  asm volatile("ldmatrix.sync.aligned.m8n8.x4.shared.b16 {%0,%1,%2,%3}, [%4];" \
      : "=r"((r)[0]), "=r"((r)[1]), "=r"((r)[2]), "=r"((r)[3]) : "r"(addr))

#define GPAD 72

template<int EPI, int BM_T, int NS>
__global__ __launch_bounds__(256, 2)
void gemm_mma(const __half* __restrict__ A, const __half* __restrict__ B,
              float* __restrict__ C, __half* __restrict__ Ch,
              const float* __restrict__ Res, const float* __restrict__ Gate,
              int M, int N, int K)
{
    constexpr int A_EL  = BM_T * GPAD;
    constexpr int B_EL  = 128 * GPAD;
    constexpr int STAGE = A_EL + B_EL;
    constexpr int MI    = BM_T / 32;

    extern __shared__ __half dyn[];
    const uint32_t dynb = smem_u32(dyn);

    const int tid  = threadIdx.x;
    const int warp = tid >> 5;
    const int lane = tid & 31;
    const int g    = lane >> 2;
    const int tig  = lane & 3;
    const int wm   = (warp >> 2) * (BM_T / 2);
    const int wn   = (warp & 3) * 32;
    const int bm   = blockIdx.y * BM_T;
    const int bn   = blockIdx.x * 128;

    const int lh = lane & 15;
    const int kh = (lane >> 4) << 3;
    const uint32_t aoff = (uint32_t)((wm + lh) * GPAD + kh) * 2;
    const uint32_t boff = (uint32_t)((wn + lh) * GPAD + kh) * 2;

    float acc[MI][4][4];
#pragma unroll
    for (int mi = 0; mi < MI; mi++)
#pragma unroll
        for (int ni = 0; ni < 4; ni++)
#pragma unroll
            for (int q = 0; q < 4; q++) acc[mi][ni][q] = 0.0f;

    const int NC = K >> 6;

    auto issue = [&](int stg, int k0) {
        const uint32_t sb = dynb + stg * STAGE * 2;
#pragma unroll
        for (int i = 0; i < BM_T / 32; i++) {
            int c = tid + i * 256;
            int row = c >> 3, cc = (c & 7) << 3;
            cp16(sb + (uint32_t)(row * GPAD + cc) * 2,
                 A + (size_t)(bm + row) * K + k0 + cc);
        }
#pragma unroll
        for (int i = 0; i < 4; i++) {
            int c = tid + i * 256;
            int row = c >> 3, cc = (c & 7) << 3;
            cp16(sb + (uint32_t)(A_EL + row * GPAD + cc) * 2,
                 B + (size_t)(bn + row) * K + k0 + cc);
        }
        asm volatile("cp.async.commit_group;" ::: "memory");
    };

#pragma unroll
    for (int p = 0; p < NS - 1; p++) issue(p, p << 6);

    for (int c = 0; c < NC; c++) {
        asm volatile("cp.async.wait_group %0;" :: "n"(NS - 2) : "memory");
        __syncthreads();
        {
            int nk = c + NS - 1;
            issue(nk % NS, (nk < NC ? nk : NC - 1) << 6);
        }

        const uint32_t sb = dynb + (c % NS) * STAGE * 2;
        const uint32_t aS = sb;
        const uint32_t bS = sb + A_EL * 2;

#pragma unroll
        for (int ks = 0; ks < 64; ks += 16) {
            const uint32_t ko = (uint32_t)ks * 2;
            uint32_t afr[MI][4], bh[4][2];
#pragma unroll
            for (int mi = 0; mi < MI; mi++)
                LDSM_X4(afr[mi], aS + aoff + (uint32_t)(mi * 16 * GPAD) * 2 + ko);
#pragma unroll
            for (int p = 0; p < 2; p++) {
                uint32_t r[4];
                LDSM_X4(r, bS + boff + (uint32_t)(p * 16 * GPAD) * 2 + ko);
                bh[2 * p][0] = r[0]; bh[2 * p][1] = r[2];
                bh[2 * p + 1][0] = r[1]; bh[2 * p + 1][1] = r[3];
            }
#pragma unroll
            for (int mi = 0; mi < MI; mi++)
#pragma unroll
                for (int ni = 0; ni < 4; ni++)
                    MMA_F16(acc[mi][ni], afr[mi], bh[ni]);
        }
    }
    asm volatile("cp.async.wait_group 0;" ::: "memory");

    // ---- epilogue ----
#pragma unroll
    for (int mi = 0; mi < MI; mi++) {
        int row = bm + wm + mi * 16 + g;
#pragma unroll
        for (int ni = 0; ni < 4; ni++) {
            int col = bn + wn + ni * 8 + tig * 2;
            float v0 = acc[mi][ni][0], v1 = acc[mi][ni][1];
            float v2 = acc[mi][ni][2], v3 = acc[mi][ni][3];
            if (EPI == 1) {
                v0 = siluf_(v0); v1 = siluf_(v1); v2 = siluf_(v2); v3 = siluf_(v3);
                *(__half2*)(Ch + (size_t)row * N + col)       = __floats2half2_rn(v0, v1);
                *(__half2*)(Ch + (size_t)(row + 8) * N + col) = __floats2half2_rn(v2, v3);
            } else if (EPI == 4) {
                float2 f0 = *(const float2*)(Res + (size_t)row * N + col);
                float2 f1 = *(const float2*)(Res + (size_t)(row + 8) * N + col);
                float2 gv0 = *(const float2*)(Gate + (size_t)row * 4096 + 2048 + col);
                float2 gv1 = *(const float2*)(Gate + (size_t)(row + 8) * 4096 + 2048 + col);
                float p0 = f0.x * sigmoidf_(v0) * siluf_(gv0.x);
                float p1 = f0.y * sigmoidf_(v1) * siluf_(gv0.y);
                float p2 = f1.x * sigmoidf_(v2) * siluf_(gv1.x);
                float p3 = f1.y * sigmoidf_(v3) * siluf_(gv1.y);
                *(__half2*)(Ch + (size_t)row * N + col)       = __floats2half2_rn(p0, p1);
                *(__half2*)(Ch + (size_t)(row + 8) * N + col) = __floats2half2_rn(p2, p3);
            } else {
                if (EPI == 3) {
                    const float2 r0v = *(const float2*)(Res + (size_t)row * N + col);
                    const float2 r1v = *(const float2*)(Res + (size_t)(row + 8) * N + col);
                    v0 += r0v.x; v1 += r0v.y; v2 += r1v.x; v3 += r1v.y;
                }
                float2 o0; o0.x = v0; o0.y = v1;
                float2 o1; o1.x = v2; o1.y = v3;
                *(float2*)(C + (size_t)row * N + col)       = o0;
                *(float2*)(C + (size_t)(row + 8) * N + col) = o1;
            }
        }
    }
}

// ---------------- merged downsample ----------------
__global__ void down_all(const float* __restrict__ xz, float* __restrict__ o1,
                         float* __restrict__ o2)
{
    int idx = blockIdx.x * blockDim.x + threadIdx.x;
    if (idx < 512 * DIN) {
        int t = idx >> 11, d = idx & 2047;
        o1[idx] = 0.5f * (xz[(size_t)(2 * t) * 4096 + d] + xz[(size_t)(2 * t + 1) * 4096 + d]);
    } else {
        int r = idx - 512 * DIN;
        int t = r >> 11, d = r & 2047;
        float s = xz[(size_t)(4 * t) * 4096 + d] + xz[(size_t)(4 * t + 1) * 4096 + d]
                + xz[(size_t)(4 * t + 2) * 4096 + d] + xz[(size_t)(4 * t + 3) * 4096 + d];
        o2[r] = 0.25f * s;
    }
}

// ---------------- fused SSM front, TB=4 t-rows per block ----------------------
// grid: 256 (scale0) + 128 (scale1) + 64 (scale2) = 448 blocks of 256 threads.
// smem: sxc[TB][DIN] fp32 (32KB) + sB[TB][16].
__global__ __launch_bounds__(256)
void ssm_front_tb(const float* __restrict__ xz, const float* __restrict__ x1,
                  const float* __restrict__ x2,
                  const float* __restrict__ cw, const float* __restrict__ cb,
                  const float* __restrict__ xw,
                  const float* __restrict__ dtw, const float* __restrict__ dtb,
                  float* __restrict__ xc, float* __restrict__ proj,
                  float* __restrict__ dt)
{
    extern __shared__ float sm[];
    float* sxc = sm;                 // TB*DIN
    float* sB  = sm + TB * DIN;      // TB*16

    const int blk = blockIdx.x;
    int sc, t0, xs; const float* src;
    if (blk < 256)      { sc = 0; t0 = blk * TB;         src = xz; xs = 4096; }
    else if (blk < 384) { sc = 1; t0 = (blk - 256) * TB; src = x1; xs = 2048; }
    else                { sc = 2; t0 = (blk - 384) * TB; src = x2; xs = 2048; }
    const int tg0 = (sc == 0 ? 0 : (sc == 1 ? 1024 : 1536)) + t0;

    // ---- stage 1: depthwise conv + silu for TB rows ----
#pragma unroll
    for (int i = 0; i < 8; i++) {
        int d = threadIdx.x + i * 256;
        float4 wv = *(const float4*)(cw + (size_t)sc * DIN * 4 + d * 4);
        float bb  = cb[sc * DIN + d];
#pragma unroll
        for (int r = 0; r < TB; r++) {
            int trow = t0 + r;
            float acc = bb;
            if (trow >= 3) acc = fmaf(src[(size_t)(trow - 3) * xs + d], wv.x, acc);
            if (trow >= 2) acc = fmaf(src[(size_t)(trow - 2) * xs + d], wv.y, acc);
            if (trow >= 1) acc = fmaf(src[(size_t)(trow - 1) * xs + d], wv.z, acc);
            acc = fmaf(src[(size_t)trow * xs + d], wv.w, acc);
            float v = acc * sigmoidf_(acc);
            sxc[r * DIN + d] = v;
            xc[(size_t)(tg0 + r) * DIN + d] = v;
        }
    }
    __syncthreads();

    // ---- stage 2: xproj — warp computes 4 outputs x TB rows, weights once ----
    {
        int warp = threadIdx.x >> 5, lane = threadIdx.x & 31;
        const float* wbase = xw + (size_t)sc * 32 * DIN;
        const float* w0 = wbase + (size_t)(warp * 4 + 0) * DIN;
        const float* w1 = wbase + (size_t)(warp * 4 + 1) * DIN;
        const float* w2 = wbase + (size_t)(warp * 4 + 2) * DIN;
        const float* w3 = wbase + (size_t)(warp * 4 + 3) * DIN;
        float a[4][TB];
#pragma unroll
        for (int j = 0; j < 4; j++)
#pragma unroll
            for (int r = 0; r < TB; r++) a[j][r] = 0.0f;
        for (int k = lane; k < DIN; k += 32) {
            float wv0 = w0[k], wv1 = w1[k], wv2 = w2[k], wv3 = w3[k];
#pragma unroll
            for (int r = 0; r < TB; r++) {
                float xv = sxc[r * DIN + k];
                a[0][r] = fmaf(xv, wv0, a[0][r]);
                a[1][r] = fmaf(xv, wv1, a[1][r]);
                a[2][r] = fmaf(xv, wv2, a[2][r]);
                a[3][r] = fmaf(xv, wv3, a[3][r]);
            }
        }
#pragma unroll
        for (int o = 16; o > 0; o >>= 1)
#pragma unroll
            for (int j = 0; j < 4; j++)
#pragma unroll
                for (int r = 0; r < TB; r++)
                    a[j][r] += __shfl_xor_sync(0xffffffffu, a[j][r], o);
        if (lane == 0) {
            int o0 = warp * 4;
#pragma unroll
            for (int r = 0; r < TB; r++) {
#pragma unroll
                for (int j = 0; j < 4; j++)
                    proj[(tg0 + r) * 32 + o0 + j] = a[j][r];
                if (o0 < 16) {
#pragma unroll
                    for (int j = 0; j < 4; j++) sB[r * 16 + o0 + j] = a[j][r];
                }
            }
        }
    }
    __syncthreads();

    // ---- stage 3: dt — dtw loads hoisted out of the row loop ----
#pragma unroll
    for (int i = 0; i < 8; i++) {
        int d = threadIdx.x + i * 256;
        const float4* wp = (const float4*)(dtw + (size_t)sc * DIN * 16 + (size_t)d * 16);
        float4 w0 = wp[0], w1 = wp[1], w2 = wp[2], w3 = wp[3];
        float bb = dtb[sc * DIN + d];
#pragma unroll
        for (int r = 0; r < TB; r++) {
            const float* B = sB + r * 16;
            float acc = bb;
            acc = fmaf(B[0],  w0.x, acc); acc = fmaf(B[1],  w0.y, acc);
            acc = fmaf(B[2],  w0.z, acc); acc = fmaf(B[3],  w0.w, acc);
            acc = fmaf(B[4],  w1.x, acc); acc = fmaf(B[5],  w1.y, acc);
            acc = fmaf(B[6],  w1.z, acc); acc = fmaf(B[7],  w1.w, acc);
            acc = fmaf(B[8],  w2.x, acc); acc = fmaf(B[9],  w2.y, acc);
            acc = fmaf(B[10], w2.z, acc); acc = fmaf(B[11], w2.w, acc);
            acc = fmaf(B[12], w3.x, acc); acc = fmaf(B[13], w3.y, acc);
            acc = fmaf(B[14], w3.z, acc); acc = fmaf(B[15], w3.w, acc);
            dt[(size_t)(tg0 + r) * DIN + d] = softplusf_(softplusf_(acc));
        }
    }
}

// ---------------- merged selective scan (all scales, 4-t batched) -------------
__global__ __launch_bounds__(256)
void scan_all(const float* __restrict__ dt, const float* __restrict__ xc,
              const float* __restrict__ proj, const float* __restrict__ Dp,
              float* __restrict__ y)
{
    int gid = blockIdx.x * blockDim.x + threadIdx.x;
    int sc  = gid >> 15;
    int r   = gid & 32767;
    int d = r >> 4;
    int s = r & 15;
    const int T    = (sc == 0) ? 1024 : (sc == 1 ? 512 : 256);
    const int toff = (sc == 0) ? 0 : (sc == 1 ? 1024 : 1536);
    const float* dts = dt   + (size_t)toff * DIN;
    const float* xcs = xc   + (size_t)toff * DIN;
    const float* prs = proj + (size_t)toff * 32;
    float*       ys  = y    + (size_t)toff * DIN;
    const float A = -(float)(s + 1);
    const float Dd = Dp[sc * DIN + d];
    float h = 0.0f;
    for (int t0 = 0; t0 < T; t0 += 4) {
        float v[4], xcv[4], dtv[4], Bv[4], Cv[4];
#pragma unroll
        for (int j = 0; j < 4; j++) {
            int t = t0 + j;
            dtv[j] = dts[(size_t)t * DIN + d];
            xcv[j] = xcs[(size_t)t * DIN + d];
            Bv[j]  = prs[t * 32 + s];
            Cv[j]  = prs[t * 32 + 16 + s];
        }
#pragma unroll
        for (int j = 0; j < 4; j++) {
            float da  = fmaxf(expf(dtv[j] * A), 1e-38f);
            float dbx = fmaxf(dtv[j] * Bv[j] * xcv[j], 1e-38f);
            h = fmaf(da, h, dbx);
            v[j] = Cv[j] * h;
        }
#pragma unroll
        for (int o = 8; o > 0; o >>= 1) {
            v[0] += __shfl_xor_sync(0xffffffffu, v[0], o, 16);
            v[1] += __shfl_xor_sync(0xffffffffu, v[1], o, 16);
            v[2] += __shfl_xor_sync(0xffffffffu, v[2], o, 16);
            v[3] += __shfl_xor_sync(0xffffffffu, v[3], o, 16);
        }
        if (s == 0) {
#pragma unroll
            for (int j = 0; j < 4; j++)
                ys[(size_t)(t0 + j) * DIN + d] = v[j] + Dd * xcv[j];
        }
    }
}

// ---------------- fuse ----------------
__global__ void fuse_kernel(const float* __restrict__ y0, const float* __restrict__ y1,
                            const float* __restrict__ y2, const float* __restrict__ sw,
                            float* __restrict__ fused, __half* __restrict__ ctxh)
{
    int idx = blockIdx.x * blockDim.x + threadIdx.x;
    int t = idx >> 11, d = idx & 2047;

    float o0 = y0[idx];

    float p1 = fminf(fmaxf(0.5f * (float)t - 0.25f, 0.0f), 511.0f);
    int lo1 = (int)floorf(p1);
    int hi1 = min(lo1 + 1, 511);
    float w1 = p1 - (float)lo1;
    float o1 = y1[(size_t)lo1 * DIN + d] * (1.0f - w1) + y1[(size_t)hi1 * DIN + d] * w1;

    float p2 = fminf(fmaxf(0.25f * (float)t - 0.375f, 0.0f), 255.0f);
    int lo2 = (int)floorf(p2);
    int hi2 = min(lo2 + 1, 255);
    float w2 = p2 - (float)lo2;
    float o2 = y2[(size_t)lo2 * DIN + d] * (1.0f - w2) + y2[(size_t)hi2 * DIN + d] * w2;

    float s0 = sw[0], s1 = sw[1], s2 = sw[2];
    float m = fmaxf(s0, fmaxf(s1, s2));
    float e0 = expf(s0 - m), e1 = expf(s1 - m), e2 = expf(s2 - m);
    float inv = 1.0f / (e0 + e1 + e2);

    fused[idx] = e0 * inv * o0 + e1 * inv * o1 + e2 * inv * o2;
    ctxh[idx]  = __float2half_rn((o0 + o1 + o2) * (1.0f / 3.0f));
}

// ---------------- layernorm ----------------
__global__ __launch_bounds__(256)
void ln_kernel(const float* __restrict__ y, const float* __restrict__ g,
               const float* __restrict__ b, float* __restrict__ out)
{
    int t = blockIdx.x;
    const float* yr = y + (size_t)t * DIMP;
    float vals[4];
    float s = 0.0f, s2 = 0.0f;
#pragma unroll
    for (int i = 0; i < 4; i++) {
        float v = yr[threadIdx.x + i * 256];
        vals[i] = v; s += v; s2 += v * v;
    }
#pragma unroll
    for (int o = 16; o > 0; o >>= 1) {
        s  += __shfl_xor_sync(0xffffffffu, s, o);
        s2 += __shfl_xor_sync(0xffffffffu, s2, o);
    }
    __shared__ float rs[8], rs2[8];
    int warp = threadIdx.x >> 5, lane = threadIdx.x & 31;
    if (lane == 0) { rs[warp] = s; rs2[warp] = s2; }
    __syncthreads();
    if (threadIdx.x == 0) {
        float S = 0, S2 = 0;
#pragma unroll
        for (int i = 0; i < 8; i++) { S += rs[i]; S2 += rs2[i]; }
        rs[0] = S; rs2[0] = S2;
    }
    __syncthreads();
    float mu  = rs[0] * (1.0f / 1024.0f);
    float var = rs2[0] * (1.0f / 1024.0f) - mu * mu;
    float rstd = rsqrtf(var + 1e-5f);
#pragma unroll
    for (int i = 0; i < 4; i++) {
        int j = threadIdx.x + i * 256;
        out[(size_t)t * DIMP + j] = (vals[i] - mu) * rstd * g[j] + b[j];
    }
}

// ---------------- launch ------------------------------------------------------
extern "C" void kernel_launch(void* const* d_in, const int* in_sizes, int n_in,
                              void* d_out, int out_size)
{
    const float* x          = (const float*)d_in[0];
    const float* in_proj_w  = (const float*)d_in[1];
    const float* conv_w     = (const float*)d_in[2];
    const float* conv_b     = (const float*)d_in[3];
    const float* xproj_w    = (const float*)d_in[4];
    const float* dtproj_w   = (const float*)d_in[5];
    const float* dtproj_b   = (const float*)d_in[6];
    const float* D_param    = (const float*)d_in[7];
    const float* scale_w    = (const float*)d_in[8];
    const float* gate_w1    = (const float*)d_in[9];
    const float* gate_w2    = (const float*)d_in[10];
    const float* out_proj_w = (const float*)d_in[11];
    const float* ln_g       = (const float*)d_in[12];
    const float* ln_b       = (const float*)d_in[13];
    float* out = (float*)d_out;

    float *xz, *x1, *x2, *xc, *proj, *dt, *yb, *fused, *yres;
    cudaGetSymbolAddress((void**)&xz,   g_xz);
    cudaGetSymbolAddress((void**)&x1,   g_x1);
    cudaGetSymbolAddress((void**)&x2,   g_x2);
    cudaGetSymbolAddress((void**)&xc,   g_xc);
    cudaGetSymbolAddress((void**)&proj, g_proj);
    cudaGetSymbolAddress((void**)&dt,   g_dt);
    cudaGetSymbolAddress((void**)&yb,   g_y);
    cudaGetSymbolAddress((void**)&fused,g_fused);
    cudaGetSymbolAddress((void**)&yres, g_yres);

    __half *xh,*ctxh,*g1h,*preh,*w0h,*w1h,*w2h,*w3h;
    cudaGetSymbolAddress((void**)&xh,  g_xh);
    cudaGetSymbolAddress((void**)&ctxh,g_ctxh);
    cudaGetSymbolAddress((void**)&g1h, g_g1h);
    cudaGetSymbolAddress((void**)&preh,g_preh);
    cudaGetSymbolAddress((void**)&w0h, g_w0h);
    cudaGetSymbolAddress((void**)&w1h, g_w1h);
    cudaGetSymbolAddress((void**)&w2h, g_w2h);
    cudaGetSymbolAddress((void**)&w3h, g_w3h);

    constexpr int SM128 = (128 * GPAD + 128 * GPAD) * 2 * 3;  // 110592 B
    constexpr int SM64  = (64  * GPAD + 128 * GPAD) * 2 * 4;  // 110592 B
    constexpr int SMFRONT = (TB * DIN + TB * 16) * 4;         // 33024 B
    cudaFuncSetAttribute(gemm_mma<0,128,3>, cudaFuncAttributeMaxDynamicSharedMemorySize, SM128);
    cudaFuncSetAttribute(gemm_mma<1,64,4>,  cudaFuncAttributeMaxDynamicSharedMemorySize, SM64);
    cudaFuncSetAttribute(gemm_mma<4,64,4>,  cudaFuncAttributeMaxDynamicSharedMemorySize, SM64);
    cudaFuncSetAttribute(gemm_mma<3,64,4>,  cudaFuncAttributeMaxDynamicSharedMemorySize, SM64);
    cudaFuncSetAttribute(ssm_front_tb,      cudaFuncAttributeMaxDynamicSharedMemorySize, SMFRONT);

    // 0) preconvert all fp16 operands in one launch
    cvt_all_kernel<<<CVT_UNITS / 256, 256>>>(x, xh, in_proj_w, w0h, gate_w1, w1h,
                                             gate_w2, w2h, out_proj_w, w3h);

    // 1) xz = x @ in_proj_w^T
    gemm_mma<0,128,3><<<dim3(32, 8), 256, SM128>>>(xh, w0h, xz, nullptr, nullptr, nullptr,
                                                   1024, 4096, 1024);

    // 2) downsample (merged)
    down_all<<<(512 * DIN + 256 * DIN) / 256, 256>>>(xz, x1, x2);

    // 3) SSM front fused (TB=4 rows/block), then scan
    ssm_front_tb<<<448, 256, SMFRONT>>>(xz, x1, x2, conv_w, conv_b, xproj_w,
                                        dtproj_w, dtproj_b, xc, proj, dt);
    scan_all<<<(3 * DIN * NSTATE) / 256, 256>>>(dt, xc, proj, D_param, yb);

    // 4) fuse
    fuse_kernel<<<(TLEN * DIN) / 256, 256>>>(yb, yb + (size_t)1024 * DIN, yb + (size_t)1536 * DIN,
                                             scale_w, fused, ctxh);

    // 5) gating (pre fused into gemm2 epilogue)
    gemm_mma<1,64,4><<<dim3(8, 16), 256, SM64>>>(ctxh, w1h, nullptr, g1h, nullptr, nullptr,
                                                 1024, 1024, 2048);
    gemm_mma<4,64,4><<<dim3(16, 16), 256, SM64>>>(g1h, w2h, nullptr, preh, fused, xz,
                                                  1024, 2048, 1024);

    // 6) out_proj + residual
    gemm_mma<3,64,4><<<dim3(8, 16), 256, SM64>>>(preh, w3h, yres, nullptr, x, nullptr,
                                                 1024, 1024, 2048);

    // 7) layernorm
    ln_kernel<<<1024, 256>>>(yres, ln_g, ln_b, out);
}